// round 1
// baseline (speedup 1.0000x reference)
#include <cuda_runtime.h>
#include <math.h>

#define HID 128
#define MAXE 800000
#define MAXN 50000

// ---- scratch (static __device__ per allocation rules) ----
__device__ float g_Y1[(size_t)MAXE * HID];     // 409.6 MB: pre-BN edge activations
__device__ float g_AGG[(size_t)MAXN * HID];    // 25.6 MB : scatter-add target
__device__ float g_H2[(size_t)MAXN * HID];     // 25.6 MB : pre-BN node activations
__device__ float g_stats1[2 * HID];            // sum / sumsq (edge BN)
__device__ float g_stats2[2 * HID];            // sum / sumsq (node BN)
__device__ float g_bn1[2 * HID];               // scale / shift (edge BN)
__device__ float g_bn2[2 * HID];               // scale / shift (node BN)

// =====================================================================
// Edge layer 1: Y1 = concat(x[row], edge_attr) @ W1a + b1a ; stats accum
// Tile: 64 edges x 128 feats, 256 threads, 8x4 register tile per thread.
// =====================================================================
__global__ __launch_bounds__(256, 2)
void k_edge_l1(const float* __restrict__ x, const int* __restrict__ row,
               const float* __restrict__ ea, const float* __restrict__ W,
               const float* __restrict__ b, int E, int nTiles)
{
    extern __shared__ float sm[];
    float* Wsm  = sm;                  // 128*128
    float* Asm  = sm + 128 * 128;      // 128*65 (A^T, pitch 65)
    float* Ssum = Asm + 128 * 65;      // 128
    float* Sssq = Ssum + 128;          // 128

    int tid = threadIdx.x;
    int tx = tid & 31, ty = tid >> 5;

    for (int i = tid; i < 128 * 128; i += 256) Wsm[i] = W[i];
    if (tid < 128) { Ssum[tid] = 0.f; Sssq[tid] = 0.f; }

    float bias[4];
#pragma unroll
    for (int f = 0; f < 4; f++) bias[f] = b[tx + 32 * f];

    float tsum[4] = {0.f, 0.f, 0.f, 0.f};
    float tssq[4] = {0.f, 0.f, 0.f, 0.f};

    for (int tile = blockIdx.x; tile < nTiles; tile += gridDim.x) {
        int e0 = tile * 64;
        __syncthreads();
        for (int idx = tid; idx < 64 * 128; idx += 256) {
            int e = idx >> 7, k = idx & 127;
            int ge = e0 + e;
            float v = 0.f;
            if (ge < E) v = (k < 64) ? x[row[ge] * 64 + k] : ea[(size_t)ge * 64 + (k - 64)];
            Asm[k * 65 + e] = v;
        }
        __syncthreads();

        float acc[8][4];
#pragma unroll
        for (int i = 0; i < 8; i++)
#pragma unroll
            for (int f = 0; f < 4; f++) acc[i][f] = bias[f];

        for (int k = 0; k < 128; k++) {
            float a[8], w[4];
#pragma unroll
            for (int i = 0; i < 8; i++) a[i] = Asm[k * 65 + ty + 8 * i];
#pragma unroll
            for (int f = 0; f < 4; f++) w[f] = Wsm[k * 128 + tx + 32 * f];
#pragma unroll
            for (int i = 0; i < 8; i++)
#pragma unroll
                for (int f = 0; f < 4; f++) acc[i][f] = fmaf(a[i], w[f], acc[i][f]);
        }

#pragma unroll
        for (int i = 0; i < 8; i++) {
            int ge = e0 + ty + 8 * i;
            if (ge < E) {
#pragma unroll
                for (int f = 0; f < 4; f++) {
                    float y = acc[i][f];
                    g_Y1[(size_t)ge * 128 + tx + 32 * f] = y;
                    tsum[f] += y;
                    tssq[f] += y * y;
                }
            }
        }
    }
    __syncthreads();
#pragma unroll
    for (int f = 0; f < 4; f++) {
        atomicAdd(&Ssum[tx + 32 * f], tsum[f]);
        atomicAdd(&Sssq[tx + 32 * f], tssq[f]);
    }
    __syncthreads();
    if (tid < 128) {
        atomicAdd(&g_stats1[tid], Ssum[tid]);
        atomicAdd(&g_stats1[128 + tid], Sssq[tid]);
    }
}

// =====================================================================
// BN finalize: scale = g*rsqrt(var+eps), shift = beta - mu*scale
// =====================================================================
__global__ void k_finalize(const float* __restrict__ stats,
                           const float* __restrict__ g,
                           const float* __restrict__ be,
                           float* __restrict__ bn, float invC)
{
    int j = threadIdx.x;  // 128
    float mu  = stats[j] * invC;
    float var = stats[128 + j] * invC - mu * mu;
    float sc  = g[j] * rsqrtf(var + 1e-5f);
    bn[j]       = sc;
    bn[128 + j] = be[j] - mu * sc;
}

// =====================================================================
// Edge layer 2: O = relu(bn(Y1)) @ W2a + b2a ; scatter-add into g_AGG[col]
// =====================================================================
__global__ __launch_bounds__(256, 2)
void k_edge_l2(const int* __restrict__ col, const float* __restrict__ W,
               const float* __restrict__ b, int E, int nTiles)
{
    extern __shared__ float sm[];
    float* Wsm = sm;                // 128*128
    float* Asm = sm + 128 * 128;    // 128*65
    float* BN  = Asm + 128 * 65;    // 256

    int tid = threadIdx.x;
    int tx = tid & 31, ty = tid >> 5;

    for (int i = tid; i < 128 * 128; i += 256) Wsm[i] = W[i];
    BN[tid] = g_bn1[tid];   // 256 threads == 256 entries

    float bias[4];
#pragma unroll
    for (int f = 0; f < 4; f++) bias[f] = b[tx + 32 * f];

    for (int tile = blockIdx.x; tile < nTiles; tile += gridDim.x) {
        int e0 = tile * 64;
        __syncthreads();
        for (int idx = tid; idx < 64 * 128; idx += 256) {
            int e = idx >> 7, k = idx & 127;
            int ge = e0 + e;
            float v = 0.f;
            if (ge < E) {
                float y = g_Y1[(size_t)ge * 128 + k];
                v = fmaxf(fmaf(y, BN[k], BN[128 + k]), 0.f);
            }
            Asm[k * 65 + e] = v;
        }
        __syncthreads();

        float acc[8][4];
#pragma unroll
        for (int i = 0; i < 8; i++)
#pragma unroll
            for (int f = 0; f < 4; f++) acc[i][f] = bias[f];

        for (int k = 0; k < 128; k++) {
            float a[8], w[4];
#pragma unroll
            for (int i = 0; i < 8; i++) a[i] = Asm[k * 65 + ty + 8 * i];
#pragma unroll
            for (int f = 0; f < 4; f++) w[f] = Wsm[k * 128 + tx + 32 * f];
#pragma unroll
            for (int i = 0; i < 8; i++)
#pragma unroll
                for (int f = 0; f < 4; f++) acc[i][f] = fmaf(a[i], w[f], acc[i][f]);
        }

#pragma unroll
        for (int i = 0; i < 8; i++) {
            int ge = e0 + ty + 8 * i;
            if (ge < E) {
                float* dst = g_AGG + (size_t)col[ge] * 128;
#pragma unroll
                for (int f = 0; f < 4; f++)
                    atomicAdd(dst + tx + 32 * f, acc[i][f]);
            }
        }
    }
}

// =====================================================================
// Node layer 1: H2 = concat(x, AGG) @ W1b + b1b ; stats accum. K = 192.
// =====================================================================
__global__ __launch_bounds__(256, 1)
void k_node_l1(const float* __restrict__ x, const float* __restrict__ W,
               const float* __restrict__ b, int N, int nTiles)
{
    extern __shared__ float sm[];
    float* Wsm  = sm;                  // 192*128
    float* Asm  = sm + 192 * 128;      // 192*65
    float* Ssum = Asm + 192 * 65;      // 128
    float* Sssq = Ssum + 128;          // 128

    int tid = threadIdx.x;
    int tx = tid & 31, ty = tid >> 5;

    for (int i = tid; i < 192 * 128; i += 256) Wsm[i] = W[i];
    if (tid < 128) { Ssum[tid] = 0.f; Sssq[tid] = 0.f; }

    float bias[4];
#pragma unroll
    for (int f = 0; f < 4; f++) bias[f] = b[tx + 32 * f];

    float tsum[4] = {0.f, 0.f, 0.f, 0.f};
    float tssq[4] = {0.f, 0.f, 0.f, 0.f};

    for (int tile = blockIdx.x; tile < nTiles; tile += gridDim.x) {
        int n0 = tile * 64;
        __syncthreads();
        for (int idx = tid; idx < 64 * 192; idx += 256) {
            int e = idx / 192, k = idx % 192;
            int gn = n0 + e;
            float v = 0.f;
            if (gn < N) v = (k < 64) ? x[gn * 64 + k] : g_AGG[(size_t)gn * 128 + (k - 64)];
            Asm[k * 65 + e] = v;
        }
        __syncthreads();

        float acc[8][4];
#pragma unroll
        for (int i = 0; i < 8; i++)
#pragma unroll
            for (int f = 0; f < 4; f++) acc[i][f] = bias[f];

        for (int k = 0; k < 192; k++) {
            float a[8], w[4];
#pragma unroll
            for (int i = 0; i < 8; i++) a[i] = Asm[k * 65 + ty + 8 * i];
#pragma unroll
            for (int f = 0; f < 4; f++) w[f] = Wsm[k * 128 + tx + 32 * f];
#pragma unroll
            for (int i = 0; i < 8; i++)
#pragma unroll
                for (int f = 0; f < 4; f++) acc[i][f] = fmaf(a[i], w[f], acc[i][f]);
        }

#pragma unroll
        for (int i = 0; i < 8; i++) {
            int gn = n0 + ty + 8 * i;
            if (gn < N) {
#pragma unroll
                for (int f = 0; f < 4; f++) {
                    float y = acc[i][f];
                    g_H2[(size_t)gn * 128 + tx + 32 * f] = y;
                    tsum[f] += y;
                    tssq[f] += y * y;
                }
            }
        }
    }
    __syncthreads();
#pragma unroll
    for (int f = 0; f < 4; f++) {
        atomicAdd(&Ssum[tx + 32 * f], tsum[f]);
        atomicAdd(&Sssq[tx + 32 * f], tssq[f]);
    }
    __syncthreads();
    if (tid < 128) {
        atomicAdd(&g_stats2[tid], Ssum[tid]);
        atomicAdd(&g_stats2[128 + tid], Sssq[tid]);
    }
}

// =====================================================================
// Node layer 2: out = relu(bn(H2)) @ W2b + b2b.  64 output feats.
// =====================================================================
__global__ __launch_bounds__(256, 2)
void k_node_l2(float* __restrict__ out, const float* __restrict__ W,
               const float* __restrict__ b, int N, int nTiles)
{
    extern __shared__ float sm[];
    float* Wsm = sm;               // 128*64
    float* Asm = sm + 128 * 64;    // 128*65
    float* BN  = Asm + 128 * 65;   // 256

    int tid = threadIdx.x;
    int tx = tid & 31, ty = tid >> 5;

    for (int i = tid; i < 128 * 64; i += 256) Wsm[i] = W[i];
    BN[tid] = g_bn2[tid];

    float bias[2];
#pragma unroll
    for (int f = 0; f < 2; f++) bias[f] = b[tx + 32 * f];

    for (int tile = blockIdx.x; tile < nTiles; tile += gridDim.x) {
        int n0 = tile * 64;
        __syncthreads();
        for (int idx = tid; idx < 64 * 128; idx += 256) {
            int e = idx >> 7, k = idx & 127;
            int gn = n0 + e;
            float v = 0.f;
            if (gn < N) {
                float y = g_H2[(size_t)gn * 128 + k];
                v = fmaxf(fmaf(y, BN[k], BN[128 + k]), 0.f);
            }
            Asm[k * 65 + e] = v;
        }
        __syncthreads();

        float acc[8][2];
#pragma unroll
        for (int i = 0; i < 8; i++)
#pragma unroll
            for (int f = 0; f < 2; f++) acc[i][f] = bias[f];

        for (int k = 0; k < 128; k++) {
            float a[8], w[2];
#pragma unroll
            for (int i = 0; i < 8; i++) a[i] = Asm[k * 65 + ty + 8 * i];
#pragma unroll
            for (int f = 0; f < 2; f++) w[f] = Wsm[k * 64 + tx + 32 * f];
#pragma unroll
            for (int i = 0; i < 8; i++)
#pragma unroll
                for (int f = 0; f < 2; f++) acc[i][f] = fmaf(a[i], w[f], acc[i][f]);
        }

#pragma unroll
        for (int i = 0; i < 8; i++) {
            int gn = n0 + ty + 8 * i;
            if (gn < N) {
#pragma unroll
                for (int f = 0; f < 2; f++)
                    out[(size_t)gn * 64 + tx + 32 * f] = acc[i][f];
            }
        }
    }
}

// =====================================================================
extern "C" void kernel_launch(void* const* d_in, const int* in_sizes, int n_in,
                              void* d_out, int out_size)
{
    const float* x    = (const float*)d_in[0];
    const int*   ei   = (const int*)d_in[1];
    const float* ea   = (const float*)d_in[2];
    const float* W1a  = (const float*)d_in[5];
    const float* b1a  = (const float*)d_in[6];
    const float* g1a  = (const float*)d_in[7];
    const float* be1a = (const float*)d_in[8];
    const float* W2a  = (const float*)d_in[9];
    const float* b2a  = (const float*)d_in[10];
    const float* W1b  = (const float*)d_in[11];
    const float* b1b  = (const float*)d_in[12];
    const float* g1b  = (const float*)d_in[13];
    const float* be1b = (const float*)d_in[14];
    const float* W2b  = (const float*)d_in[15];
    const float* b2b  = (const float*)d_in[16];

    int N = in_sizes[0] / 64;
    int E = in_sizes[1] / 2;
    const int* row = ei;
    const int* col = ei + E;

    // scratch symbol addresses (host-side, capture-time only)
    void *pS1, *pS2, *pAGG, *pBN1, *pBN2;
    cudaGetSymbolAddress(&pS1, g_stats1);
    cudaGetSymbolAddress(&pS2, g_stats2);
    cudaGetSymbolAddress(&pAGG, g_AGG);
    cudaGetSymbolAddress(&pBN1, g_bn1);
    cudaGetSymbolAddress(&pBN2, g_bn2);

    const int SM_EDGE = (128 * 128 + 128 * 65 + 256) * 4;   // 99840 B
    const int SM_N1   = (192 * 128 + 192 * 65 + 256) * 4;   // 149248 B
    const int SM_N2   = (128 * 64 + 128 * 65 + 256) * 4;    // 67072 B

    cudaFuncSetAttribute(k_edge_l1, cudaFuncAttributeMaxDynamicSharedMemorySize, SM_EDGE);
    cudaFuncSetAttribute(k_edge_l2, cudaFuncAttributeMaxDynamicSharedMemorySize, SM_EDGE);
    cudaFuncSetAttribute(k_node_l1, cudaFuncAttributeMaxDynamicSharedMemorySize, SM_N1);
    cudaFuncSetAttribute(k_node_l2, cudaFuncAttributeMaxDynamicSharedMemorySize, SM_N2);

    // zero accumulators (memset nodes are graph-capturable)
    cudaMemsetAsync(pS1, 0, 2 * HID * sizeof(float), 0);
    cudaMemsetAsync(pS2, 0, 2 * HID * sizeof(float), 0);
    cudaMemsetAsync(pAGG, 0, (size_t)N * HID * sizeof(float), 0);

    int tilesE = (E + 63) / 64;
    int tilesN = (N + 63) / 64;

    k_edge_l1<<<592, 256, SM_EDGE>>>(x, row, ea, W1a, b1a, E, tilesE);
    k_finalize<<<1, 128>>>((const float*)pS1, g1a, be1a, (float*)pBN1, 1.0f / (float)E);
    k_edge_l2<<<592, 256, SM_EDGE>>>(col, W2a, b2a, E, tilesE);
    k_node_l1<<<296, 256, SM_N1>>>(x, W1b, b1b, N, tilesN);
    k_finalize<<<1, 128>>>((const float*)pS2, g1b, be1b, (float*)pBN2, 1.0f / (float)N);
    k_node_l2<<<296, 256, SM_N2>>>((float*)d_out, W2b, b2b, N, tilesN);
}